// round 16
// baseline (speedup 1.0000x reference)
#include <cuda_runtime.h>
#include <cuda_bf16.h>
#include <cstdint>

#define GK   192
#define NPIX 65536

// ---------------------------------------------------------------------------
// scratch (allocation-free rule: __device__ globals)
// ---------------------------------------------------------------------------
__device__ float g_qkv[75497472];                         // [2][65536][576] f32 (pixel-major)
__device__ __align__(16) unsigned short g_bth[25165824];  // [2][65536][192] bf16 hi
__device__ __align__(16) unsigned short g_btl[25165824];  // [2][65536][192] bf16 lo
__device__ __align__(16) unsigned short g_wqh[110592], g_wql[110592];
__device__ __align__(16) unsigned short g_wph[36864],  g_wpl[36864];

// ---------------------------------------------------------------------------
__device__ __forceinline__ uint32_t smem_u32(const void* p) {
    uint32_t a;
    asm("{ .reg .u64 t; cvta.to.shared.u64 t, %1; cvt.u32.u64 %0, t; }"
        : "=r"(a) : "l"(p));
    return a;
}

__device__ __forceinline__ void cp_async16(uint32_t dst, const void* src) {
    asm volatile("cp.async.cg.shared.global [%0], [%1], 16;"
                 :: "r"(dst), "l"(src) : "memory");
}

#define LDSM_X4(r0, r1, r2, r3, a) \
    asm volatile("ldmatrix.sync.aligned.m8n8.x4.shared.b16 {%0,%1,%2,%3}, [%4];" \
                 : "=r"(r0), "=r"(r1), "=r"(r2), "=r"(r3) : "r"(a))

#define MMA16816(d, a, b) \
    asm volatile("mma.sync.aligned.m16n8k16.row.col.f32.bf16.bf16.f32 " \
                 "{%0,%1,%2,%3}, {%4,%5,%6,%7}, {%8,%9}, {%0,%1,%2,%3};" \
                 : "+f"((d)[0]), "+f"((d)[1]), "+f"((d)[2]), "+f"((d)[3]) \
                 : "r"((a)[0]), "r"((a)[1]), "r"((a)[2]), "r"((a)[3]), \
                   "r"((b)[0]), "r"((b)[1]))

// hygienic float4 FMA
__device__ __forceinline__ void f4fma(float4& o, const float4 h, const float4 wv) {
    o.x = fmaf(h.x, wv.x, o.x);
    o.y = fmaf(h.y, wv.y, o.y);
    o.z = fmaf(h.z, wv.z, o.z);
    o.w = fmaf(h.w, wv.w, o.w);
}

// ---------------------------------------------------------------------------
// convert + transpose: src f32 [2][192][65536] -> dhi/dlo bf16 [2][65536][192]
// ---------------------------------------------------------------------------
__global__ __launch_bounds__(256) void convtrans(
    const float* __restrict__ src,
    unsigned short* __restrict__ dhi,
    unsigned short* __restrict__ dlo)
{
    __shared__ float sm[32][33];
    const int p0 = blockIdx.x * 32, c0 = blockIdx.y * 32, b = blockIdx.z;
    const float* s = src + (size_t)b * GK * NPIX;
    const int tc = threadIdx.x & 31, tr = threadIdx.x >> 5;

    #pragma unroll
    for (int i = 0; i < 4; i++) {
        int cl = tr + i * 8;
        sm[cl][tc] = s[(size_t)(c0 + cl) * NPIX + p0 + tc];
    }
    __syncthreads();

    const size_t obase = (size_t)b * NPIX * GK;
    #pragma unroll
    for (int i = 0; i < 4; i++) {
        int pl = tr + i * 8;
        float v = sm[tc][pl];
        __nv_bfloat16 h = __float2bfloat16(v);
        __nv_bfloat16 l = __float2bfloat16(v - __bfloat162float(h));
        size_t o = obase + (size_t)(p0 + pl) * GK + c0 + tc;
        dhi[o] = *(unsigned short*)&h;
        dlo[o] = *(unsigned short*)&l;
    }
}

__global__ void wconvert(const float* __restrict__ w, int n,
                         unsigned short* __restrict__ hi,
                         unsigned short* __restrict__ lo)
{
    int i = blockIdx.x * 256 + threadIdx.x;
    if (i < n) {
        float v = w[i];
        __nv_bfloat16 h = __float2bfloat16(v);
        __nv_bfloat16 l = __float2bfloat16(v - __bfloat162float(h));
        hi[i] = *(unsigned short*)&h;
        lo[i] = *(unsigned short*)&l;
    }
}

// ---------------------------------------------------------------------------
// qkv GEMM, pixel-major output (unchanged)
// ---------------------------------------------------------------------------
__global__ __launch_bounds__(256) void gemm_nt(
    const unsigned short* __restrict__ Ahi,
    const unsigned short* __restrict__ Alo,
    const unsigned short* __restrict__ Whi,
    const unsigned short* __restrict__ Wlo,
    float* __restrict__ Cm, int Ntot)
{
    extern __shared__ __align__(16) unsigned short smem[];
    const int t = threadIdx.x, lane = t & 31, w = t >> 5;
    const int bN = blockIdx.x * 64;
    const size_t bM = (size_t)blockIdx.y * 128;
    const int batch = blockIdx.z;
    const int wm0 = (w & 3) * 32;
    const int wn0 = (w >> 2) * 32;

    const uint32_t sb = smem_u32(smem);
    const size_t aoff = ((size_t)batch * NPIX + bM) * GK;
    const unsigned short* gA[2] = { Ahi + aoff, Alo + aoff };
    const unsigned short* gW[2] = { Whi + (size_t)bN * GK, Wlo + (size_t)bN * GK };

    auto issue_chunk = [&](int c) {
        const uint32_t sbase = sb + (uint32_t)(c & 1) * 30720u;
        #pragma unroll
        for (int i = 0; i < 4; i++) {
            int id = t + i * 256;
            int hl = id >> 9, rem = id & 511;
            int row = rem >> 2, c8 = rem & 3;
            uint32_t d = sbase + (uint32_t)(hl * 5120 + row * 40 + c8 * 8) * 2u;
            cp_async16(d, gA[hl] + row * GK + c * 32 + c8 * 8);
        }
        #pragma unroll
        for (int i = 0; i < 2; i++) {
            int id = t + i * 256;
            int hl = id >> 8, rem = id & 255;
            int row = rem >> 2, c8 = rem & 3;
            uint32_t d = sbase + (uint32_t)(10240 + hl * 2560 + row * 40 + c8 * 8) * 2u;
            cp_async16(d, gW[hl] + row * GK + c * 32 + c8 * 8);
        }
        asm volatile("cp.async.commit_group;" ::: "memory");
    };

    float acc[2][4][4];
    #pragma unroll
    for (int mi = 0; mi < 2; mi++)
        #pragma unroll
        for (int ni = 0; ni < 4; ni++)
            #pragma unroll
            for (int r = 0; r < 4; r++) acc[mi][ni][r] = 0.f;

    const int arow  = lane & 15;
    const int akoff = (lane >> 4) * 8;
    const int bg    = lane >> 3;
    const int brow8 = lane & 7;

    issue_chunk(0);
    #pragma unroll 1
    for (int c = 0; c < 6; c++) {
        asm volatile("cp.async.wait_group 0;" ::: "memory");
        __syncthreads();
        if (c + 1 < 6) issue_chunk(c + 1);

        const uint32_t sbase = sb + (uint32_t)(c & 1) * 30720u;
        #pragma unroll
        for (int ks = 0; ks < 2; ks++) {
            const int k0 = ks * 16;
            uint32_t ah[2][4], al[2][4], bh[4][2], bl[4][2];
            #pragma unroll
            for (int mi = 0; mi < 2; mi++) {
                uint32_t off = (uint32_t)((wm0 + mi * 16 + arow) * 40 + k0 + akoff) * 2u;
                LDSM_X4(ah[mi][0], ah[mi][1], ah[mi][2], ah[mi][3], sbase + off);
                LDSM_X4(al[mi][0], al[mi][1], al[mi][2], al[mi][3],
                        sbase + 5120u * 2u + off);
            }
            #pragma unroll
            for (int np = 0; np < 2; np++) {
                uint32_t off = (uint32_t)(10240
                    + (wn0 + (2 * np + (bg >> 1)) * 8 + brow8) * 40
                    + k0 + (bg & 1) * 8) * 2u;
                LDSM_X4(bh[2*np][0], bh[2*np][1], bh[2*np+1][0], bh[2*np+1][1],
                        sbase + off);
                LDSM_X4(bl[2*np][0], bl[2*np][1], bl[2*np+1][0], bl[2*np+1][1],
                        sbase + 2560u * 2u + off);
            }
            #pragma unroll
            for (int mi = 0; mi < 2; mi++)
                #pragma unroll
                for (int ni = 0; ni < 4; ni++)
                    MMA16816(acc[mi][ni], ah[mi], bh[ni]);
            #pragma unroll
            for (int mi = 0; mi < 2; mi++)
                #pragma unroll
                for (int ni = 0; ni < 4; ni++)
                    MMA16816(acc[mi][ni], ah[mi], bl[ni]);
            #pragma unroll
            for (int mi = 0; mi < 2; mi++)
                #pragma unroll
                for (int ni = 0; ni < 4; ni++)
                    MMA16816(acc[mi][ni], al[mi], bh[ni]);
        }
    }

    float* C = Cm + (size_t)batch * NPIX * (size_t)Ntot;
    const int mr = lane >> 2, nc = (lane & 3) * 2;
    #pragma unroll
    for (int mi = 0; mi < 2; mi++)
        #pragma unroll
        for (int ni = 0; ni < 4; ni++) {
            const size_t m = bM + wm0 + mi * 16 + mr;
            const size_t n = (size_t)(bN + wn0 + ni * 8 + nc);
            float* a = acc[mi][ni];
            *(float2*)&C[m * Ntot + n]       = make_float2(a[0], a[1]);
            *(float2*)&C[(m + 8) * Ntot + n] = make_float2(a[2], a[3]);
        }
}

// ---------------------------------------------------------------------------
// proj GEMM (unchanged)
// ---------------------------------------------------------------------------
__global__ __launch_bounds__(256) void gemm_mma(
    const unsigned short* __restrict__ Ahi,
    const unsigned short* __restrict__ Alo,
    const unsigned short* __restrict__ Bhi,
    const unsigned short* __restrict__ Blo,
    float* __restrict__ Cm, int Mtot)
{
    extern __shared__ __align__(16) unsigned short smem[];
    const int t = threadIdx.x, lane = t & 31, w = t >> 5;
    const int bM = blockIdx.x * 64;
    const size_t bN = (size_t)blockIdx.y * 128;
    const int batch = blockIdx.z;
    const int wm0 = (w >> 2) * 32;
    const int wn0 = (w & 3) * 32;

    const uint32_t sb = smem_u32(smem);
    const unsigned short* gA[2] = { Ahi + (size_t)bM * GK, Alo + (size_t)bM * GK };
    const size_t boff = ((size_t)batch * NPIX + bN) * GK;
    const unsigned short* gB[2] = { Bhi + boff, Blo + boff };

    auto issue_chunk = [&](int c) {
        const uint32_t sbase = sb + (uint32_t)(c & 1) * 30720u;
        #pragma unroll
        for (int i = 0; i < 2; i++) {
            int id = t + i * 256;
            int hl = id >> 8, rem = id & 255;
            int row = rem >> 2, c8 = rem & 3;
            uint32_t d = sbase + (uint32_t)(hl * 2560 + row * 40 + c8 * 8) * 2u;
            cp_async16(d, gA[hl] + row * GK + c * 32 + c8 * 8);
        }
        #pragma unroll
        for (int i = 0; i < 4; i++) {
            int id = t + i * 256;
            int hl = id >> 9, rem = id & 511;
            int row = rem >> 2, c8 = rem & 3;
            uint32_t d = sbase + (uint32_t)(5120 + hl * 5120 + row * 40 + c8 * 8) * 2u;
            cp_async16(d, gB[hl] + row * GK + c * 32 + c8 * 8);
        }
        asm volatile("cp.async.commit_group;" ::: "memory");
    };

    float acc[2][4][4];
    #pragma unroll
    for (int mi = 0; mi < 2; mi++)
        #pragma unroll
        for (int ni = 0; ni < 4; ni++)
            #pragma unroll
            for (int r = 0; r < 4; r++) acc[mi][ni][r] = 0.f;

    const int arow  = lane & 15;
    const int akoff = (lane >> 4) * 8;
    const int bg    = lane >> 3;
    const int brow8 = lane & 7;

    issue_chunk(0);
    #pragma unroll 1
    for (int c = 0; c < 6; c++) {
        asm volatile("cp.async.wait_group 0;" ::: "memory");
        __syncthreads();
        if (c + 1 < 6) issue_chunk(c + 1);

        const uint32_t sbase = sb + (uint32_t)(c & 1) * 30720u;
        #pragma unroll
        for (int ks = 0; ks < 2; ks++) {
            const int k0 = ks * 16;
            uint32_t ah[2][4], al[2][4], bh[4][2], bl[4][2];
            #pragma unroll
            for (int mi = 0; mi < 2; mi++) {
                uint32_t off = (uint32_t)((wm0 + mi * 16 + arow) * 40 + k0 + akoff) * 2u;
                LDSM_X4(ah[mi][0], ah[mi][1], ah[mi][2], ah[mi][3], sbase + off);
                LDSM_X4(al[mi][0], al[mi][1], al[mi][2], al[mi][3],
                        sbase + 2560u * 2u + off);
            }
            #pragma unroll
            for (int np = 0; np < 2; np++) {
                uint32_t off = (uint32_t)(5120
                    + (wn0 + (2 * np + (bg >> 1)) * 8 + brow8) * 40
                    + k0 + (bg & 1) * 8) * 2u;
                LDSM_X4(bh[2*np][0], bh[2*np][1], bh[2*np+1][0], bh[2*np+1][1],
                        sbase + off);
                LDSM_X4(bl[2*np][0], bl[2*np][1], bl[2*np+1][0], bl[2*np+1][1],
                        sbase + 5120u * 2u + off);
            }
            #pragma unroll
            for (int mi = 0; mi < 2; mi++)
                #pragma unroll
                for (int ni = 0; ni < 4; ni++)
                    MMA16816(acc[mi][ni], ah[mi], bh[ni]);
            #pragma unroll
            for (int mi = 0; mi < 2; mi++)
                #pragma unroll
                for (int ni = 0; ni < 4; ni++)
                    MMA16816(acc[mi][ni], ah[mi], bl[ni]);
            #pragma unroll
            for (int mi = 0; mi < 2; mi++)
                #pragma unroll
                for (int ni = 0; ni < 4; ni++)
                    MMA16816(acc[mi][ni], al[mi], bh[ni]);
        }
    }

    float* C = Cm + (size_t)batch * (size_t)Mtot * NPIX;
    const int mr = lane >> 2, nc = (lane & 3) * 2;
    #pragma unroll
    for (int mi = 0; mi < 2; mi++)
        #pragma unroll
        for (int ni = 0; ni < 4; ni++) {
            const size_t m = (size_t)(bM + wm0 + mi * 16 + mr);
            const size_t n = bN + wn0 + ni * 8 + nc;
            float* a = acc[mi][ni];
            *(float2*)&C[m * NPIX + n]       = make_float2(a[0], a[1]);
            *(float2*)&C[(m + 8) * NPIX + n] = make_float2(a[2], a[3]);
        }
}

// ---------------------------------------------------------------------------
// Fused depthwise-3x3 + window channel attention.
// Conv: R15 vertical 4-px tasks (conflict-free). NEW: logits 6i x 4j @ 96thr
// (broadcast-q lane map), PV 6i x 8d @ 64thr with conflict-free d-split
// (td*4, td*4+32). Crossbar bytes ~-25% vs R15.
// ---------------------------------------------------------------------------
#define ATTN_SMEM_FLOATS (3072 + 3328 + 3072 + 2800 + 216 + 48 + 48)
__global__ __launch_bounds__(256) void window_attn(
    const float* __restrict__ dww,    // [576*9]
    const float* __restrict__ tempr)  // [4]
{
    extern __shared__ __align__(16) float dsm[];
    float* sq      = dsm;              // [48 ch][64 px]
    float* skT     = dsm + 3072;       // [64 px][52 ch]
    float* sv      = dsm + 6400;       // [48 ch][64 px]
    float* scratch = dsm + 9472;       // halo [100][28] -> sattn [48][52]
    float* w4s     = dsm + 12272;      // [9][24]
    float* qin     = dsm + 12488;
    float* kin     = dsm + 12536;

    const int t    = threadIdx.x;
    const int head = blockIdx.x & 3;
    const int win  = blockIdx.x >> 2;
    const int b    = win >> 10;
    const int hn   = (win >> 5) & 31;
    const int wn   = win & 31;
    const int y0   = hn << 3, x0 = wn << 3;

    const size_t pixbase = (size_t)b * NPIX;

    float4 hreg4[3];
    auto load_halo = [&](int chbase) {
        #pragma unroll
        for (int i = 0; i < 3; i++) {
            int e = t + i * 256;
            float4 v = make_float4(0.f, 0.f, 0.f, 0.f);
            if (e < 600) {
                int px = e / 6, c4 = e - px * 6;
                int iy = px / 10, ix = px - iy * 10;
                int gy = y0 - 1 + iy, gx = x0 - 1 + ix;
                if ((unsigned)gy < 256u && (unsigned)gx < 256u)
                    v = *(const float4*)&g_qkv[
                        (pixbase + (size_t)gy * 256 + gx) * 576 + chbase + c4 * 4];
            }
            hreg4[i] = v;
        }
    };
    auto chbase_of = [&](int p) {
        return (p >> 1) * 192 + head * 48 + (p & 1) * 24;
    };

    load_halo(chbase_of(0));
    #pragma unroll 1
    for (int p = 0; p < 6; p++) {
        const int tensor = p >> 1;
        const int half   = p & 1;
        const int gch0   = tensor * 192 + head * 48 + half * 24;

        if (t < 216) {
            int k = t / 24, c = t - k * 24;
            w4s[k * 24 + c] = dww[(gch0 + c) * 9 + k];
        }
        #pragma unroll
        for (int i = 0; i < 3; i++) {
            int e = t + i * 256;
            if (e < 600) {
                int px = e / 6, c4 = e - px * 6;
                *(float4*)&scratch[px * 28 + c4 * 4] = hreg4[i];
            }
        }
        __syncthreads();

        if (p < 5) load_halo(chbase_of(p + 1));

        // conv: 96 tasks; task = (c4 group, column p2, 4-row stack)
        if (t < 96) {
            const int c4g  = t >> 4;
            const int rem  = t & 15;
            const int p1s  = (rem >> 3) * 4;
            const int p2   = rem & 7;
            float4 wv[9];
            #pragma unroll
            for (int k = 0; k < 9; k++)
                wv[k] = *(const float4*)&w4s[k * 24 + c4g * 4];
            float4 o[4];
            #pragma unroll
            for (int i = 0; i < 4; i++) o[i] = make_float4(0.f, 0.f, 0.f, 0.f);

            #pragma unroll
            for (int r = 0; r < 6; r++) {
                const float* hrow = scratch + ((p1s + r) * 10 + p2) * 28 + c4g * 4;
                float4 ha = *(const float4*)&hrow[0];
                float4 hb = *(const float4*)&hrow[28];
                float4 hc = *(const float4*)&hrow[56];
                #pragma unroll
                for (int dy = 0; dy < 3; dy++) {
                    const int i = r - dy;
                    if (i >= 0 && i < 4) {
                        f4fma(o[i], ha, wv[dy * 3 + 0]);
                        f4fma(o[i], hb, wv[dy * 3 + 1]);
                        f4fma(o[i], hc, wv[dy * 3 + 2]);
                    }
                }
            }
            const int ch = half * 24 + c4g * 4;
            #pragma unroll
            for (int i = 0; i < 4; i++) {
                const int px = (p1s + i) * 8 + p2;
                if (tensor == 0) {
                    sq[(ch + 0) * 64 + px] = o[i].x;
                    sq[(ch + 1) * 64 + px] = o[i].y;
                    sq[(ch + 2) * 64 + px] = o[i].z;
                    sq[(ch + 3) * 64 + px] = o[i].w;
                } else if (tensor == 1) {
                    *(float4*)&skT[px * 52 + ch] = o[i];
                } else {
                    sv[(ch + 0) * 64 + px] = o[i].x;
                    sv[(ch + 1) * 64 + px] = o[i].y;
                    sv[(ch + 2) * 64 + px] = o[i].z;
                    sv[(ch + 3) * 64 + px] = o[i].w;
                }
            }
        }
        __syncthreads();
    }

    // ---- l2 norms: 2 threads per channel, shfl combine ----
    if (t < 96) {
        const int c = t >> 1, half = t & 1;
        float s = 0.f;
        #pragma unroll 8
        for (int i = 0; i < 32; i++) {
            int idx = (i + (t >> 1) + half * 16) & 31;
            float x = sq[c * 64 + half * 32 + idx];
            s = fmaf(x, x, s);
        }
        s += __shfl_xor_sync(0xffffffff, s, 1);
        if (half == 0) qin[c] = 1.f / fmaxf(sqrtf(s), 1e-12f);
    } else if (t >= 128 && t < 224) {
        const int j = (t - 128) >> 1, half = t & 1;
        float s = 0.f;
        #pragma unroll 8
        for (int i = 0; i < 32; i++) {
            int d = half * 32 + ((i + half * 4) & 31);
            float x = skT[d * 52 + j];
            s = fmaf(x, x, s);
        }
        s += __shfl_xor_sync(0xffffffff, s, 1);
        if (half == 0) kin[j] = 1.f / fmaxf(sqrtf(s), 1e-12f);
    }
    __syncthreads();

    float* sattn = scratch;                        // [48][52]
    const float tscale = __ldg(&tempr[head]);

    // ---- logits: 96 threads, 6i x 4j tile (broadcast-q lane map) ----
    if (t < 96) {
        const int ti = t / 12, tj = t - ti * 12;
        const int i0 = ti * 6, j0 = tj * 4;
        float acc[6][4];
        #pragma unroll
        for (int r = 0; r < 6; r++)
            #pragma unroll
            for (int s = 0; s < 4; s++) acc[r][s] = 0.f;

        for (int d0 = 0; d0 < 64; d0 += 4) {
            float4 qv[6];
            #pragma unroll
            for (int r = 0; r < 6; r++)
                qv[r] = *(const float4*)&sq[(i0 + r) * 64 + d0];
            #pragma unroll
            for (int dd = 0; dd < 4; dd++) {
                float4 kv = *(const float4*)&skT[(d0 + dd) * 52 + j0];
                #pragma unroll
                for (int r = 0; r < 6; r++) {
                    float qd = (dd == 0) ? qv[r].x : (dd == 1) ? qv[r].y
                             : (dd == 2) ? qv[r].z : qv[r].w;
                    acc[r][0] = fmaf(qd, kv.x, acc[r][0]);
                    acc[r][1] = fmaf(qd, kv.y, acc[r][1]);
                    acc[r][2] = fmaf(qd, kv.z, acc[r][2]);
                    acc[r][3] = fmaf(qd, kv.w, acc[r][3]);
                }
            }
        }
        float k0s = kin[j0], k1s = kin[j0 + 1], k2s = kin[j0 + 2], k3s = kin[j0 + 3];
        #pragma unroll
        for (int r = 0; r < 6; r++) {
            float qi = qin[i0 + r] * tscale;
            *(float4*)&sattn[(i0 + r) * 52 + j0] = make_float4(
                acc[r][0] * qi * k0s, acc[r][1] * qi * k1s,
                acc[r][2] * qi * k2s, acc[r][3] * qi * k3s);
        }
    }
    __syncthreads();

    // ---- softmax: 2 threads per row (24 logits each), shfl combine ----
    if (t < 96) {
        const int r = t >> 1, half = t & 1;
        float4 row[6];
        float m = -1e30f;
        #pragma unroll
        for (int g = 0; g < 6; g++) {
            row[g] = *(const float4*)&sattn[r * 52 + half * 24 + g * 4];
            m = fmaxf(m, fmaxf(fmaxf(row[g].x, row[g].y),
                               fmaxf(row[g].z, row[g].w)));
        }
        m = fmaxf(m, __shfl_xor_sync(0xffffffff, m, 1));
        float s = 0.f;
        #pragma unroll
        for (int g = 0; g < 6; g++) {
            row[g].x = __expf(row[g].x - m);
            row[g].y = __expf(row[g].y - m);
            row[g].z = __expf(row[g].z - m);
            row[g].w = __expf(row[g].w - m);
            s += row[g].x + row[g].y + row[g].z + row[g].w;
        }
        s += __shfl_xor_sync(0xffffffff, s, 1);
        float inv = 1.f / s;
        #pragma unroll
        for (int g = 0; g < 6; g++) {
            row[g].x *= inv; row[g].y *= inv;
            row[g].z *= inv; row[g].w *= inv;
            *(float4*)&sattn[r * 52 + half * 24 + g * 4] = row[g];
        }
    }
    __syncthreads();

    // ---- out = attn @ v ; 64 threads, 6i x 8d, d-split (td*4, td*4+32) ----
    uint32_t* stg = (uint32_t*)skT;                // [64 px][52 ch]
    {
        const int td = t & 7, ti = t >> 3;
        const int d0 = td * 4, i0 = ti * 6;
        float acc[6][8];
        if (t < 64) {
            #pragma unroll
            for (int r = 0; r < 6; r++)
                #pragma unroll
                for (int s = 0; s < 8; s++) acc[r][s] = 0.f;

            #pragma unroll 2
            for (int jg = 0; jg < 12; jg++) {
                const int j = jg * 4;
                float4 av[6];
                #pragma unroll
                for (int r = 0; r < 6; r++)
                    av[r] = *(const float4*)&sattn[(i0 + r) * 52 + j];
                #pragma unroll
                for (int jj = 0; jj < 4; jj++) {
                    float4 v0 = *(const float4*)&sv[(j + jj) * 64 + d0];
                    float4 v1 = *(const float4*)&sv[(j + jj) * 64 + d0 + 32];
                    #pragma unroll
                    for (int r = 0; r < 6; r++) {
                        float a = (jj == 0) ? av[r].x : (jj == 1) ? av[r].y
                                : (jj == 2) ? av[r].z : av[r].w;
                        acc[r][0] = fmaf(a, v0.x, acc[r][0]);
                        acc[r][1] = fmaf(a, v0.y, acc[r][1]);
                        acc[r][2] = fmaf(a, v0.z, acc[r][2]);
                        acc[r][3] = fmaf(a, v0.w, acc[r][3]);
                        acc[r][4] = fmaf(a, v1.x, acc[r][4]);
                        acc[r][5] = fmaf(a, v1.y, acc[r][5]);
                        acc[r][6] = fmaf(a, v1.z, acc[r][6]);
                        acc[r][7] = fmaf(a, v1.w, acc[r][7]);
                    }
                }
            }
        }
        __syncthreads();                           // skT readers done
        if (t < 64) {
            #pragma unroll
            for (int r = 0; r < 6; r++)
                #pragma unroll
                for (int s = 0; s < 8; s++) {
                    const int px = (s < 4) ? (d0 + s) : (d0 + 32 + s - 4);
                    float v = acc[r][s];
                    __nv_bfloat16 h = __float2bfloat16(v);
                    __nv_bfloat16 l = __float2bfloat16(v - __bfloat162float(h));
                    stg[px * 52 + i0 + r] =
                        (uint32_t)*(unsigned short*)&h
                        | ((uint32_t)*(unsigned short*)&l << 16);
                }
        }
    }
    __syncthreads();

    // cooperative transposed writeout -> g_bth/g_btl [b][pix][192]
    #pragma unroll
    for (int i = 0; i < 6; i++) {
        int id = t + i * 256;
        int row = id / 24, cp = id - row * 24;
        int c = cp * 2;
        uint32_t w0 = stg[row * 52 + c];
        uint32_t w1 = stg[row * 52 + c + 1];
        int p1 = row >> 3, p2 = row & 7;
        size_t o = (pixbase + (size_t)(y0 + p1) * 256 + (x0 + p2)) * GK
                 + head * 48 + c;
        *(ushort2*)&g_bth[o] = make_ushort2((unsigned short)w0, (unsigned short)w1);
        *(ushort2*)&g_btl[o] = make_ushort2((unsigned short)(w0 >> 16),
                                            (unsigned short)(w1 >> 16));
    }
}

// ---------------------------------------------------------------------------
extern "C" void kernel_launch(void* const* d_in, const int* in_sizes, int n_in,
                              void* d_out, int out_size)
{
    const float *x = nullptr, *qw = nullptr, *dw = nullptr, *pw = nullptr, *tp = nullptr;
    for (int i = 0; i < n_in; i++) {
        switch (in_sizes[i]) {
            case 25165824: x  = (const float*)d_in[i]; break;  // x [2,192,256,256]
            case 110592:   qw = (const float*)d_in[i]; break;  // qkv_w [576,192]
            case 5184:     dw = (const float*)d_in[i]; break;  // dw_w [576,1,3,3]
            case 36864:    pw = (const float*)d_in[i]; break;  // proj_w [192,192]
            case 4:        tp = (const float*)d_in[i]; break;  // temperature [4]
        }
    }

    void *qkvp, *bthp, *btlp, *wqhp, *wqlp, *wphp, *wplp;
    cudaGetSymbolAddress(&qkvp, g_qkv);
    cudaGetSymbolAddress(&bthp, g_bth);
    cudaGetSymbolAddress(&btlp, g_btl);
    cudaGetSymbolAddress(&wqhp, g_wqh);
    cudaGetSymbolAddress(&wqlp, g_wql);
    cudaGetSymbolAddress(&wphp, g_wph);
    cudaGetSymbolAddress(&wplp, g_wpl);

    const int GEMM_SMEM = 2 * 30720;               // 61440 B -> 3 CTAs/SM
    const int ATTN_SMEM = ATTN_SMEM_FLOATS * 4;    // 50336 B -> 4 CTAs/SM
    cudaFuncSetAttribute(gemm_nt,  cudaFuncAttributeMaxDynamicSharedMemorySize, GEMM_SMEM);
    cudaFuncSetAttribute(gemm_mma, cudaFuncAttributeMaxDynamicSharedMemorySize, GEMM_SMEM);
    cudaFuncSetAttribute(window_attn, cudaFuncAttributeMaxDynamicSharedMemorySize, ATTN_SMEM);

    wconvert<<<(110592 + 255) / 256, 256>>>(qw, 110592,
        (unsigned short*)wqhp, (unsigned short*)wqlp);
    wconvert<<<(36864 + 255) / 256, 256>>>(pw, 36864,
        (unsigned short*)wphp, (unsigned short*)wplp);

    // 1) x -> x^T bf16 hi/lo  ([b][pix][192])
    convtrans<<<dim3(2048, 6, 2), 256>>>(x,
        (unsigned short*)bthp, (unsigned short*)btlp);

    // 2) qkv GEMM, pixel-major output: g_qkv[b][pix][576]
    gemm_nt<<<dim3(9, 512, 2), 256, GEMM_SMEM>>>(
        (const unsigned short*)bthp, (const unsigned short*)btlp,
        (const unsigned short*)wqhp, (const unsigned short*)wqlp,
        (float*)qkvp, 576);

    // 3) fused depthwise 3x3 + attention; writes bf16 hi/lo transposed
    window_attn<<<8192, 256, ATTN_SMEM>>>(dw, tp);

    // 4) proj GEMM -> d_out ([b][192][65536], ch-major)
    gemm_mma<<<dim3(3, 512, 2), 256, GEMM_SMEM>>>(
        (const unsigned short*)wphp, (const unsigned short*)wplp,
        (const unsigned short*)bthp, (const unsigned short*)btlp,
        (float*)d_out, 192);
}

// round 17
// speedup vs baseline: 1.0319x; 1.0319x over previous
#include <cuda_runtime.h>
#include <cuda_bf16.h>
#include <cstdint>

#define GK   192
#define NPIX 65536

// ---------------------------------------------------------------------------
// scratch (allocation-free rule: __device__ globals)
// ---------------------------------------------------------------------------
__device__ float g_qkv[75497472];                         // [2][65536][576] f32 (pixel-major)
__device__ __align__(16) unsigned short g_bth[25165824];  // [2][65536][192] bf16 hi
__device__ __align__(16) unsigned short g_btl[25165824];  // [2][65536][192] bf16 lo
__device__ __align__(16) unsigned short g_wqh[110592], g_wql[110592];
__device__ __align__(16) unsigned short g_wph[36864],  g_wpl[36864];

// ---------------------------------------------------------------------------
__device__ __forceinline__ uint32_t smem_u32(const void* p) {
    uint32_t a;
    asm("{ .reg .u64 t; cvta.to.shared.u64 t, %1; cvt.u32.u64 %0, t; }"
        : "=r"(a) : "l"(p));
    return a;
}

__device__ __forceinline__ void cp_async16(uint32_t dst, const void* src) {
    asm volatile("cp.async.cg.shared.global [%0], [%1], 16;"
                 :: "r"(dst), "l"(src) : "memory");
}

#define LDSM_X4(r0, r1, r2, r3, a) \
    asm volatile("ldmatrix.sync.aligned.m8n8.x4.shared.b16 {%0,%1,%2,%3}, [%4];" \
                 : "=r"(r0), "=r"(r1), "=r"(r2), "=r"(r3) : "r"(a))

#define MMA16816(d, a, b) \
    asm volatile("mma.sync.aligned.m16n8k16.row.col.f32.bf16.bf16.f32 " \
                 "{%0,%1,%2,%3}, {%4,%5,%6,%7}, {%8,%9}, {%0,%1,%2,%3};" \
                 : "+f"((d)[0]), "+f"((d)[1]), "+f"((d)[2]), "+f"((d)[3]) \
                 : "r"((a)[0]), "r"((a)[1]), "r"((a)[2]), "r"((a)[3]), \
                   "r"((b)[0]), "r"((b)[1]))

// hygienic float4 FMA
__device__ __forceinline__ void f4fma(float4& o, const float4 h, const float4 wv) {
    o.x = fmaf(h.x, wv.x, o.x);
    o.y = fmaf(h.y, wv.y, o.y);
    o.z = fmaf(h.z, wv.z, o.z);
    o.w = fmaf(h.w, wv.w, o.w);
}

// ---------------------------------------------------------------------------
// convert + transpose: src f32 [2][192][65536] -> dhi/dlo bf16 [2][65536][192]
// 64-px x 32-ch tiles (half the CTAs of the 32x32 version).
// ---------------------------------------------------------------------------
__global__ __launch_bounds__(256) void convtrans(
    const float* __restrict__ src,
    unsigned short* __restrict__ dhi,
    unsigned short* __restrict__ dlo)
{
    __shared__ float sm[32][65];
    const int p0 = blockIdx.x * 64, c0 = blockIdx.y * 32, b = blockIdx.z;
    const float* s = src + (size_t)b * GK * NPIX;
    const int t = threadIdx.x;

    {   // load: coalesced along pixels; 64 px x 32 ch, 8 per thread
        const int pxl = t & 63, chq = t >> 6;     // chq 0..3
        #pragma unroll
        for (int i = 0; i < 8; i++) {
            int ch = chq + i * 4;
            sm[ch][pxl] = s[(size_t)(c0 + ch) * NPIX + p0 + pxl];
        }
    }
    __syncthreads();

    {   // store: coalesced along channels; 8 px per thread
        const int ch = t & 31, pxq = t >> 5;      // pxq 0..7
        const size_t obase = (size_t)b * NPIX * GK;
        #pragma unroll
        for (int i = 0; i < 8; i++) {
            int px = pxq + i * 8;
            float v = sm[ch][px];
            __nv_bfloat16 h = __float2bfloat16(v);
            __nv_bfloat16 l = __float2bfloat16(v - __bfloat162float(h));
            size_t o = obase + (size_t)(p0 + px) * GK + c0 + ch;
            dhi[o] = *(unsigned short*)&h;
            dlo[o] = *(unsigned short*)&l;
        }
    }
}

__global__ void wconvert(const float* __restrict__ w, int n,
                         unsigned short* __restrict__ hi,
                         unsigned short* __restrict__ lo)
{
    int i = blockIdx.x * 256 + threadIdx.x;
    if (i < n) {
        float v = w[i];
        __nv_bfloat16 h = __float2bfloat16(v);
        __nv_bfloat16 l = __float2bfloat16(v - __bfloat162float(h));
        hi[i] = *(unsigned short*)&h;
        lo[i] = *(unsigned short*)&l;
    }
}

// ---------------------------------------------------------------------------
// qkv GEMM, pixel-major output (unchanged, R12-proven)
// ---------------------------------------------------------------------------
__global__ __launch_bounds__(256) void gemm_nt(
    const unsigned short* __restrict__ Ahi,
    const unsigned short* __restrict__ Alo,
    const unsigned short* __restrict__ Whi,
    const unsigned short* __restrict__ Wlo,
    float* __restrict__ Cm, int Ntot)
{
    extern __shared__ __align__(16) unsigned short smem[];
    const int t = threadIdx.x, lane = t & 31, w = t >> 5;
    const int bN = blockIdx.x * 64;
    const size_t bM = (size_t)blockIdx.y * 128;
    const int batch = blockIdx.z;
    const int wm0 = (w & 3) * 32;
    const int wn0 = (w >> 2) * 32;

    const uint32_t sb = smem_u32(smem);
    const size_t aoff = ((size_t)batch * NPIX + bM) * GK;
    const unsigned short* gA[2] = { Ahi + aoff, Alo + aoff };
    const unsigned short* gW[2] = { Whi + (size_t)bN * GK, Wlo + (size_t)bN * GK };

    auto issue_chunk = [&](int c) {
        const uint32_t sbase = sb + (uint32_t)(c & 1) * 30720u;
        #pragma unroll
        for (int i = 0; i < 4; i++) {
            int id = t + i * 256;
            int hl = id >> 9, rem = id & 511;
            int row = rem >> 2, c8 = rem & 3;
            uint32_t d = sbase + (uint32_t)(hl * 5120 + row * 40 + c8 * 8) * 2u;
            cp_async16(d, gA[hl] + row * GK + c * 32 + c8 * 8);
        }
        #pragma unroll
        for (int i = 0; i < 2; i++) {
            int id = t + i * 256;
            int hl = id >> 8, rem = id & 255;
            int row = rem >> 2, c8 = rem & 3;
            uint32_t d = sbase + (uint32_t)(10240 + hl * 2560 + row * 40 + c8 * 8) * 2u;
            cp_async16(d, gW[hl] + row * GK + c * 32 + c8 * 8);
        }
        asm volatile("cp.async.commit_group;" ::: "memory");
    };

    float acc[2][4][4];
    #pragma unroll
    for (int mi = 0; mi < 2; mi++)
        #pragma unroll
        for (int ni = 0; ni < 4; ni++)
            #pragma unroll
            for (int r = 0; r < 4; r++) acc[mi][ni][r] = 0.f;

    const int arow  = lane & 15;
    const int akoff = (lane >> 4) * 8;
    const int bg    = lane >> 3;
    const int brow8 = lane & 7;

    issue_chunk(0);
    #pragma unroll 1
    for (int c = 0; c < 6; c++) {
        asm volatile("cp.async.wait_group 0;" ::: "memory");
        __syncthreads();
        if (c + 1 < 6) issue_chunk(c + 1);

        const uint32_t sbase = sb + (uint32_t)(c & 1) * 30720u;
        #pragma unroll
        for (int ks = 0; ks < 2; ks++) {
            const int k0 = ks * 16;
            uint32_t ah[2][4], al[2][4], bh[4][2], bl[4][2];
            #pragma unroll
            for (int mi = 0; mi < 2; mi++) {
                uint32_t off = (uint32_t)((wm0 + mi * 16 + arow) * 40 + k0 + akoff) * 2u;
                LDSM_X4(ah[mi][0], ah[mi][1], ah[mi][2], ah[mi][3], sbase + off);
                LDSM_X4(al[mi][0], al[mi][1], al[mi][2], al[mi][3],
                        sbase + 5120u * 2u + off);
            }
            #pragma unroll
            for (int np = 0; np < 2; np++) {
                uint32_t off = (uint32_t)(10240
                    + (wn0 + (2 * np + (bg >> 1)) * 8 + brow8) * 40
                    + k0 + (bg & 1) * 8) * 2u;
                LDSM_X4(bh[2*np][0], bh[2*np][1], bh[2*np+1][0], bh[2*np+1][1],
                        sbase + off);
                LDSM_X4(bl[2*np][0], bl[2*np][1], bl[2*np+1][0], bl[2*np+1][1],
                        sbase + 2560u * 2u + off);
            }
            #pragma unroll
            for (int mi = 0; mi < 2; mi++)
                #pragma unroll
                for (int ni = 0; ni < 4; ni++)
                    MMA16816(acc[mi][ni], ah[mi], bh[ni]);
            #pragma unroll
            for (int mi = 0; mi < 2; mi++)
                #pragma unroll
                for (int ni = 0; ni < 4; ni++)
                    MMA16816(acc[mi][ni], ah[mi], bl[ni]);
            #pragma unroll
            for (int mi = 0; mi < 2; mi++)
                #pragma unroll
                for (int ni = 0; ni < 4; ni++)
                    MMA16816(acc[mi][ni], al[mi], bh[ni]);
        }
    }

    float* C = Cm + (size_t)batch * NPIX * (size_t)Ntot;
    const int mr = lane >> 2, nc = (lane & 3) * 2;
    #pragma unroll
    for (int mi = 0; mi < 2; mi++)
        #pragma unroll
        for (int ni = 0; ni < 4; ni++) {
            const size_t m = bM + wm0 + mi * 16 + mr;
            const size_t n = (size_t)(bN + wn0 + ni * 8 + nc);
            float* a = acc[mi][ni];
            *(float2*)&C[m * Ntot + n]       = make_float2(a[0], a[1]);
            *(float2*)&C[(m + 8) * Ntot + n] = make_float2(a[2], a[3]);
        }
}

// ---------------------------------------------------------------------------
// proj GEMM (unchanged, R12-proven)
// ---------------------------------------------------------------------------
__global__ __launch_bounds__(256) void gemm_mma(
    const unsigned short* __restrict__ Ahi,
    const unsigned short* __restrict__ Alo,
    const unsigned short* __restrict__ Bhi,
    const unsigned short* __restrict__ Blo,
    float* __restrict__ Cm, int Mtot)
{
    extern __shared__ __align__(16) unsigned short smem[];
    const int t = threadIdx.x, lane = t & 31, w = t >> 5;
    const int bM = blockIdx.x * 64;
    const size_t bN = (size_t)blockIdx.y * 128;
    const int batch = blockIdx.z;
    const int wm0 = (w >> 2) * 32;
    const int wn0 = (w & 3) * 32;

    const uint32_t sb = smem_u32(smem);
    const unsigned short* gA[2] = { Ahi + (size_t)bM * GK, Alo + (size_t)bM * GK };
    const size_t boff = ((size_t)batch * NPIX + bN) * GK;
    const unsigned short* gB[2] = { Bhi + boff, Blo + boff };

    auto issue_chunk = [&](int c) {
        const uint32_t sbase = sb + (uint32_t)(c & 1) * 30720u;
        #pragma unroll
        for (int i = 0; i < 2; i++) {
            int id = t + i * 256;
            int hl = id >> 8, rem = id & 255;
            int row = rem >> 2, c8 = rem & 3;
            uint32_t d = sbase + (uint32_t)(hl * 2560 + row * 40 + c8 * 8) * 2u;
            cp_async16(d, gA[hl] + row * GK + c * 32 + c8 * 8);
        }
        #pragma unroll
        for (int i = 0; i < 4; i++) {
            int id = t + i * 256;
            int hl = id >> 9, rem = id & 511;
            int row = rem >> 2, c8 = rem & 3;
            uint32_t d = sbase + (uint32_t)(5120 + hl * 5120 + row * 40 + c8 * 8) * 2u;
            cp_async16(d, gB[hl] + row * GK + c * 32 + c8 * 8);
        }
        asm volatile("cp.async.commit_group;" ::: "memory");
    };

    float acc[2][4][4];
    #pragma unroll
    for (int mi = 0; mi < 2; mi++)
        #pragma unroll
        for (int ni = 0; ni < 4; ni++)
            #pragma unroll
            for (int r = 0; r < 4; r++) acc[mi][ni][r] = 0.f;

    const int arow  = lane & 15;
    const int akoff = (lane >> 4) * 8;
    const int bg    = lane >> 3;
    const int brow8 = lane & 7;

    issue_chunk(0);
    #pragma unroll 1
    for (int c = 0; c < 6; c++) {
        asm volatile("cp.async.wait_group 0;" ::: "memory");
        __syncthreads();
        if (c + 1 < 6) issue_chunk(c + 1);

        const uint32_t sbase = sb + (uint32_t)(c & 1) * 30720u;
        #pragma unroll
        for (int ks = 0; ks < 2; ks++) {
            const int k0 = ks * 16;
            uint32_t ah[2][4], al[2][4], bh[4][2], bl[4][2];
            #pragma unroll
            for (int mi = 0; mi < 2; mi++) {
                uint32_t off = (uint32_t)((wm0 + mi * 16 + arow) * 40 + k0 + akoff) * 2u;
                LDSM_X4(ah[mi][0], ah[mi][1], ah[mi][2], ah[mi][3], sbase + off);
                LDSM_X4(al[mi][0], al[mi][1], al[mi][2], al[mi][3],
                        sbase + 2560u * 2u + off);
            }
            #pragma unroll
            for (int np = 0; np < 2; np++) {
                uint32_t off = (uint32_t)(5120
                    + (wn0 + (2 * np + (bg >> 1)) * 8 + brow8) * 40
                    + k0 + (bg & 1) * 8) * 2u;
                LDSM_X4(bh[2*np][0], bh[2*np][1], bh[2*np+1][0], bh[2*np+1][1],
                        sbase + off);
                LDSM_X4(bl[2*np][0], bl[2*np][1], bl[2*np+1][0], bl[2*np+1][1],
                        sbase + 5120u * 2u + off);
            }
            #pragma unroll
            for (int mi = 0; mi < 2; mi++)
                #pragma unroll
                for (int ni = 0; ni < 4; ni++)
                    MMA16816(acc[mi][ni], ah[mi], bh[ni]);
            #pragma unroll
            for (int mi = 0; mi < 2; mi++)
                #pragma unroll
                for (int ni = 0; ni < 4; ni++)
                    MMA16816(acc[mi][ni], ah[mi], bl[ni]);
            #pragma unroll
            for (int mi = 0; mi < 2; mi++)
                #pragma unroll
                for (int ni = 0; ni < 4; ni++)
                    MMA16816(acc[mi][ni], al[mi], bh[ni]);
        }
    }

    float* C = Cm + (size_t)batch * (size_t)Mtot * NPIX;
    const int mr = lane >> 2, nc = (lane & 3) * 2;
    #pragma unroll
    for (int mi = 0; mi < 2; mi++)
        #pragma unroll
        for (int ni = 0; ni < 4; ni++) {
            const size_t m = (size_t)(bM + wm0 + mi * 16 + mr);
            const size_t n = bN + wn0 + ni * 8 + nc;
            float* a = acc[mi][ni];
            *(float2*)&C[m * NPIX + n]       = make_float2(a[0], a[1]);
            *(float2*)&C[(m + 8) * NPIX + n] = make_float2(a[2], a[3]);
        }
}

// ---------------------------------------------------------------------------
// Fused depthwise-3x3 + window channel attention (R15-proven config).
// Conv: vertical 4-px tasks (conflict-free). Logits 3i x 4j @ 192 thr,
// PV 3i x 4d @ 256 thr. NEW: q-norm uses rotated float4 loads.
// ---------------------------------------------------------------------------
#define ATTN_SMEM_FLOATS (3072 + 3328 + 3072 + 2800 + 216 + 48 + 48)
__global__ __launch_bounds__(256) void window_attn(
    const float* __restrict__ dww,    // [576*9]
    const float* __restrict__ tempr)  // [4]
{
    extern __shared__ __align__(16) float dsm[];
    float* sq      = dsm;              // [48 ch][64 px]
    float* skT     = dsm + 3072;       // [64 px][52 ch]
    float* sv      = dsm + 6400;       // [48 ch][64 px]
    float* scratch = dsm + 9472;       // halo [100][28] -> sattn [48][52]
    float* w4s     = dsm + 12272;      // [9][24]
    float* qin     = dsm + 12488;
    float* kin     = dsm + 12536;

    const int t    = threadIdx.x;
    const int head = blockIdx.x & 3;
    const int win  = blockIdx.x >> 2;
    const int b    = win >> 10;
    const int hn   = (win >> 5) & 31;
    const int wn   = win & 31;
    const int y0   = hn << 3, x0 = wn << 3;

    const size_t pixbase = (size_t)b * NPIX;

    float4 hreg4[3];
    auto load_halo = [&](int chbase) {
        #pragma unroll
        for (int i = 0; i < 3; i++) {
            int e = t + i * 256;
            float4 v = make_float4(0.f, 0.f, 0.f, 0.f);
            if (e < 600) {
                int px = e / 6, c4 = e - px * 6;
                int iy = px / 10, ix = px - iy * 10;
                int gy = y0 - 1 + iy, gx = x0 - 1 + ix;
                if ((unsigned)gy < 256u && (unsigned)gx < 256u)
                    v = *(const float4*)&g_qkv[
                        (pixbase + (size_t)gy * 256 + gx) * 576 + chbase + c4 * 4];
            }
            hreg4[i] = v;
        }
    };
    auto chbase_of = [&](int p) {
        return (p >> 1) * 192 + head * 48 + (p & 1) * 24;
    };

    load_halo(chbase_of(0));
    #pragma unroll 1
    for (int p = 0; p < 6; p++) {
        const int tensor = p >> 1;
        const int half   = p & 1;
        const int gch0   = tensor * 192 + head * 48 + half * 24;

        if (t < 216) {
            int k = t / 24, c = t - k * 24;
            w4s[k * 24 + c] = dww[(gch0 + c) * 9 + k];
        }
        #pragma unroll
        for (int i = 0; i < 3; i++) {
            int e = t + i * 256;
            if (e < 600) {
                int px = e / 6, c4 = e - px * 6;
                *(float4*)&scratch[px * 28 + c4 * 4] = hreg4[i];
            }
        }
        __syncthreads();

        if (p < 5) load_halo(chbase_of(p + 1));

        // conv: 96 tasks; task = (c4 group, column p2, 4-row stack)
        if (t < 96) {
            const int c4g  = t >> 4;
            const int rem  = t & 15;
            const int p1s  = (rem >> 3) * 4;
            const int p2   = rem & 7;
            float4 wv[9];
            #pragma unroll
            for (int k = 0; k < 9; k++)
                wv[k] = *(const float4*)&w4s[k * 24 + c4g * 4];
            float4 o[4];
            #pragma unroll
            for (int i = 0; i < 4; i++) o[i] = make_float4(0.f, 0.f, 0.f, 0.f);

            #pragma unroll
            for (int r = 0; r < 6; r++) {
                const float* hrow = scratch + ((p1s + r) * 10 + p2) * 28 + c4g * 4;
                float4 ha = *(const float4*)&hrow[0];
                float4 hb = *(const float4*)&hrow[28];
                float4 hc = *(const float4*)&hrow[56];
                #pragma unroll
                for (int dy = 0; dy < 3; dy++) {
                    const int i = r - dy;
                    if (i >= 0 && i < 4) {
                        f4fma(o[i], ha, wv[dy * 3 + 0]);
                        f4fma(o[i], hb, wv[dy * 3 + 1]);
                        f4fma(o[i], hc, wv[dy * 3 + 2]);
                    }
                }
            }
            const int ch = half * 24 + c4g * 4;
            #pragma unroll
            for (int i = 0; i < 4; i++) {
                const int px = (p1s + i) * 8 + p2;
                if (tensor == 0) {
                    sq[(ch + 0) * 64 + px] = o[i].x;
                    sq[(ch + 1) * 64 + px] = o[i].y;
                    sq[(ch + 2) * 64 + px] = o[i].z;
                    sq[(ch + 3) * 64 + px] = o[i].w;
                } else if (tensor == 1) {
                    *(float4*)&skT[px * 52 + ch] = o[i];
                } else {
                    sv[(ch + 0) * 64 + px] = o[i].x;
                    sv[(ch + 1) * 64 + px] = o[i].y;
                    sv[(ch + 2) * 64 + px] = o[i].z;
                    sv[(ch + 3) * 64 + px] = o[i].w;
                }
            }
        }
        __syncthreads();
    }

    // ---- l2 norms: 2 threads/channel; q side via rotated float4 loads ----
    if (t < 96) {
        const int c = t >> 1, half = t & 1;
        float s = 0.f;
        #pragma unroll
        for (int g = 0; g < 8; g++) {
            int idx = ((g + c + half * 4) & 7) * 4;     // distinct granules/phase
            float4 v = *(const float4*)&sq[c * 64 + half * 32 + idx];
            s = fmaf(v.x, v.x, s);
            s = fmaf(v.y, v.y, s);
            s = fmaf(v.z, v.z, s);
            s = fmaf(v.w, v.w, s);
        }
        s += __shfl_xor_sync(0xffffffff, s, 1);
        if (half == 0) qin[c] = 1.f / fmaxf(sqrtf(s), 1e-12f);
    } else if (t >= 128 && t < 224) {
        const int j = (t - 128) >> 1, half = t & 1;
        float s = 0.f;
        #pragma unroll 8
        for (int i = 0; i < 32; i++) {
            int d = half * 32 + ((i + half * 4) & 31);
            float x = skT[d * 52 + j];
            s = fmaf(x, x, s);
        }
        s += __shfl_xor_sync(0xffffffff, s, 1);
        if (half == 0) kin[j] = 1.f / fmaxf(sqrtf(s), 1e-12f);
    }
    __syncthreads();

    float* sattn = scratch;                        // [48][52]
    const float tscale = __ldg(&tempr[head]);

    // ---- logits: 192 threads, 3i x 4j tile ----
    if (t < 192) {
        const int ti = t / 12, tj = t - ti * 12;
        const int i0 = ti * 3, j0 = tj * 4;
        float acc[3][4];
        #pragma unroll
        for (int r = 0; r < 3; r++)
            #pragma unroll
            for (int s = 0; s < 4; s++) acc[r][s] = 0.f;

        for (int d0 = 0; d0 < 64; d0 += 4) {
            float4 qv[3];
            #pragma unroll
            for (int r = 0; r < 3; r++)
                qv[r] = *(const float4*)&sq[(i0 + r) * 64 + d0];
            #pragma unroll
            for (int dd = 0; dd < 4; dd++) {
                float4 kv = *(const float4*)&skT[(d0 + dd) * 52 + j0];
                #pragma unroll
                for (int r = 0; r < 3; r++) {
                    float qd = (dd == 0) ? qv[r].x : (dd == 1) ? qv[r].y
                             : (dd == 2) ? qv[r].z : qv[r].w;
                    acc[r][0] = fmaf(qd, kv.x, acc[r][0]);
                    acc[r][1] = fmaf(qd, kv.y, acc[r][1]);
                    acc[r][2] = fmaf(qd, kv.z, acc[r][2]);
                    acc[r][3] = fmaf(qd, kv.w, acc[r][3]);
                }
            }
        }
        float k0s = kin[j0], k1s = kin[j0 + 1], k2s = kin[j0 + 2], k3s = kin[j0 + 3];
        #pragma unroll
        for (int r = 0; r < 3; r++) {
            float qi = qin[i0 + r] * tscale;
            *(float4*)&sattn[(i0 + r) * 52 + j0] = make_float4(
                acc[r][0] * qi * k0s, acc[r][1] * qi * k1s,
                acc[r][2] * qi * k2s, acc[r][3] * qi * k3s);
        }
    }
    __syncthreads();

    // ---- softmax: 2 threads per row (24 logits each), shfl combine ----
    if (t < 96) {
        const int r = t >> 1, half = t & 1;
        float4 row[6];
        float m = -1e30f;
        #pragma unroll
        for (int g = 0; g < 6; g++) {
            row[g] = *(const float4*)&sattn[r * 52 + half * 24 + g * 4];
            m = fmaxf(m, fmaxf(fmaxf(row[g].x, row[g].y),
                               fmaxf(row[g].z, row[g].w)));
        }
        m = fmaxf(m, __shfl_xor_sync(0xffffffff, m, 1));
        float s = 0.f;
        #pragma unroll
        for (int g = 0; g < 6; g++) {
            row[g].x = __expf(row[g].x - m);
            row[g].y = __expf(row[g].y - m);
            row[g].z = __expf(row[g].z - m);
            row[g].w = __expf(row[g].w - m);
            s += row[g].x + row[g].y + row[g].z + row[g].w;
        }
        s += __shfl_xor_sync(0xffffffff, s, 1);
        float inv = 1.f / s;
        #pragma unroll
        for (int g = 0; g < 6; g++) {
            row[g].x *= inv; row[g].y *= inv;
            row[g].z *= inv; row[g].w *= inv;
            *(float4*)&sattn[r * 52 + half * 24 + g * 4] = row[g];
        }
    }
    __syncthreads();

    // ---- out = attn @ v ; 3i x 4d tile (256 threads, R12-proven) ----
    uint32_t* stg = (uint32_t*)skT;                // [64 px][52 ch]
    {
        const int td = t & 15;
        const int ti = t >> 4;
        const int d0 = td * 4, i0 = ti * 3;
        float acc[3][4];
        #pragma unroll
        for (int r = 0; r < 3; r++)
            #pragma unroll
            for (int s = 0; s < 4; s++) acc[r][s] = 0.f;

        #pragma unroll 2
        for (int jg = 0; jg < 12; jg++) {
            const int j = jg * 4;
            float4 a0 = *(const float4*)&sattn[(i0 + 0) * 52 + j];
            float4 a1 = *(const float4*)&sattn[(i0 + 1) * 52 + j];
            float4 a2 = *(const float4*)&sattn[(i0 + 2) * 52 + j];
            float4 v0 = *(const float4*)&sv[(j + 0) * 64 + d0];
            float4 v1 = *(const float4*)&sv[(j + 1) * 64 + d0];
            float4 v2 = *(const float4*)&sv[(j + 2) * 64 + d0];
            float4 v3 = *(const float4*)&sv[(j + 3) * 64 + d0];
            #pragma unroll
            for (int r = 0; r < 3; r++) {
                float4 a = (r == 0) ? a0 : (r == 1) ? a1 : a2;
                acc[r][0] = fmaf(a.x, v0.x, acc[r][0]);
                acc[r][1] = fmaf(a.x, v0.y, acc[r][1]);
                acc[r][2] = fmaf(a.x, v0.z, acc[r][2]);
                acc[r][3] = fmaf(a.x, v0.w, acc[r][3]);
                acc[r][0] = fmaf(a.y, v1.x, acc[r][0]);
                acc[r][1] = fmaf(a.y, v1.y, acc[r][1]);
                acc[r][2] = fmaf(a.y, v1.z, acc[r][2]);
                acc[r][3] = fmaf(a.y, v1.w, acc[r][3]);
                acc[r][0] = fmaf(a.z, v2.x, acc[r][0]);
                acc[r][1] = fmaf(a.z, v2.y, acc[r][1]);
                acc[r][2] = fmaf(a.z, v2.z, acc[r][2]);
                acc[r][3] = fmaf(a.z, v2.w, acc[r][3]);
                acc[r][0] = fmaf(a.w, v3.x, acc[r][0]);
                acc[r][1] = fmaf(a.w, v3.y, acc[r][1]);
                acc[r][2] = fmaf(a.w, v3.z, acc[r][2]);
                acc[r][3] = fmaf(a.w, v3.w, acc[r][3]);
            }
        }
        __syncthreads();                           // skT readers done
        #pragma unroll
        for (int r = 0; r < 3; r++)
            #pragma unroll
            for (int s = 0; s < 4; s++) {
                float v = acc[r][s];
                __nv_bfloat16 h = __float2bfloat16(v);
                __nv_bfloat16 l = __float2bfloat16(v - __bfloat162float(h));
                stg[(d0 + s) * 52 + i0 + r] =
                    (uint32_t)*(unsigned short*)&h
                    | ((uint32_t)*(unsigned short*)&l << 16);
            }
    }
    __syncthreads();

    // cooperative transposed writeout -> g_bth/g_btl [b][pix][192]
    #pragma unroll
    for (int i = 0; i < 6; i++) {
        int id = t + i * 256;
        int row = id / 24, cp = id - row * 24;
        int c = cp * 2;
        uint32_t w0 = stg[row * 52 + c];
        uint32_t w1 = stg[row * 52 + c + 1];
        int p1 = row >> 3, p2 = row & 7;
        size_t o = (pixbase + (size_t)(y0 + p1) * 256 + (x0 + p2)) * GK
                 + head * 48 + c;
        *(ushort2*)&g_bth[o] = make_ushort2((unsigned short)w0, (unsigned short)w1);
        *(ushort2*)&g_btl[o] = make_ushort2((unsigned short)(w0 >> 16),
                                            (unsigned short)(w1 >> 16));
    }
}

// ---------------------------------------------------------------------------
extern "C" void kernel_launch(void* const* d_in, const int* in_sizes, int n_in,
                              void* d_out, int out_size)
{
    const float *x = nullptr, *qw = nullptr, *dw = nullptr, *pw = nullptr, *tp = nullptr;
    for (int i = 0; i < n_in; i++) {
        switch (in_sizes[i]) {
            case 25165824: x  = (const float*)d_in[i]; break;  // x [2,192,256,256]
            case 110592:   qw = (const float*)d_in[i]; break;  // qkv_w [576,192]
            case 5184:     dw = (const float*)d_in[i]; break;  // dw_w [576,1,3,3]
            case 36864:    pw = (const float*)d_in[i]; break;  // proj_w [192,192]
            case 4:        tp = (const float*)d_in[i]; break;  // temperature [4]
        }
    }

    void *qkvp, *bthp, *btlp, *wqhp, *wqlp, *wphp, *wplp;
    cudaGetSymbolAddress(&qkvp, g_qkv);
    cudaGetSymbolAddress(&bthp, g_bth);
    cudaGetSymbolAddress(&btlp, g_btl);
    cudaGetSymbolAddress(&wqhp, g_wqh);
    cudaGetSymbolAddress(&wqlp, g_wql);
    cudaGetSymbolAddress(&wphp, g_wph);
    cudaGetSymbolAddress(&wplp, g_wpl);

    const int GEMM_SMEM = 2 * 30720;               // 61440 B -> 3 CTAs/SM
    const int ATTN_SMEM = ATTN_SMEM_FLOATS * 4;    // 50336 B -> 4 CTAs/SM
    cudaFuncSetAttribute(gemm_nt,  cudaFuncAttributeMaxDynamicSharedMemorySize, GEMM_SMEM);
    cudaFuncSetAttribute(gemm_mma, cudaFuncAttributeMaxDynamicSharedMemorySize, GEMM_SMEM);
    cudaFuncSetAttribute(window_attn, cudaFuncAttributeMaxDynamicSharedMemorySize, ATTN_SMEM);

    wconvert<<<(110592 + 255) / 256, 256>>>(qw, 110592,
        (unsigned short*)wqhp, (unsigned short*)wqlp);
    wconvert<<<(36864 + 255) / 256, 256>>>(pw, 36864,
        (unsigned short*)wphp, (unsigned short*)wplp);

    // 1) x -> x^T bf16 hi/lo  ([b][pix][192])
    convtrans<<<dim3(1024, 6, 2), 256>>>(x,
        (unsigned short*)bthp, (unsigned short*)btlp);

    // 2) qkv GEMM, pixel-major output: g_qkv[b][pix][576]
    gemm_nt<<<dim3(9, 512, 2), 256, GEMM_SMEM>>>(
        (const unsigned short*)bthp, (const unsigned short*)btlp,
        (const unsigned short*)wqhp, (const unsigned short*)wqlp,
        (float*)qkvp, 576);

    // 3) fused depthwise 3x3 + attention; writes bf16 hi/lo transposed
    window_attn<<<8192, 256, ATTN_SMEM>>>(dw, tp);

    // 4) proj GEMM -> d_out ([b][192][65536], ch-major)
    gemm_mma<<<dim3(3, 512, 2), 256, GEMM_SMEM>>>(
        (const unsigned short*)wphp, (const unsigned short*)wplp,
        (const unsigned short*)bthp, (const unsigned short*)btlp,
        (float*)d_out, 192);
}